// round 12
// baseline (speedup 1.0000x reference)
#include <cuda_runtime.h>
#include <cstdint>

// ---------------- scratch (device globals; no allocation allowed) ----------------
__device__ float g_y1[4*32*64*64];   // cv1 output
__device__ float g_y [4*64*64*64];   // cv2 output
__device__ float g_q [4*4096*8];     // q[b][n][8]
__device__ float g_k [4*4096*8];     // k[b][n][8]
__device__ float g_v [4*4096*64];    // v[b][n][64]

__device__ __forceinline__ float silu_f(float t) {
    return t * (1.0f / (1.0f + __expf(-t)));
}
__device__ __forceinline__ uint32_t f2bf2(float lo, float hi) {
    uint32_t r;
    asm("cvt.rn.bf16x2.f32 %0, %1, %2;" : "=r"(r) : "f"(hi), "f"(lo));
    return r;
}
__device__ __forceinline__ uint32_t smem_u32(const void* p) {
    uint32_t a;
    asm("{ .reg .u64 t; cvta.to.shared.u64 t, %1; cvt.u32.u64 %0, t; }" : "=r"(a) : "l"(p));
    return a;
}
__device__ __forceinline__ float to_tf32(float x) {
    uint32_t r;
    asm("cvt.rna.tf32.f32 %0, %1;" : "=r"(r) : "f"(x));
    return __uint_as_float(r);
}
__device__ __forceinline__ void mma_tf32(float c[4], uint32_t a0, uint32_t a1,
                                         uint32_t a2, uint32_t a3,
                                         uint32_t b0, uint32_t b1) {
    asm volatile(
        "mma.sync.aligned.m16n8k8.row.col.f32.tf32.tf32.f32 "
        "{%0,%1,%2,%3}, {%4,%5,%6,%7}, {%8,%9}, {%0,%1,%2,%3};"
        : "+f"(c[0]), "+f"(c[1]), "+f"(c[2]), "+f"(c[3])
        : "r"(a0), "r"(a1), "r"(a2), "r"(a3), "r"(b0), "r"(b1));
}

// ======== conv1: 3x3+BN+SiLU tf32 TC, 8x8 tile, grid 256 (R11 exact) ========
__global__ void __launch_bounds__(256, 2) conv1_kernel(
        const float* __restrict__ xin, const float* __restrict__ w,
        const float* __restrict__ bg, const float* __restrict__ bb,
        const float* __restrict__ bm, const float* __restrict__ bv,
        float* __restrict__ out) {
    constexpr int WSTR = 32*9 + 8;   // 296
    extern __shared__ __align__(16) float sm[];
    float* x_s = sm;                 // 3840 floats
    float* w_s = sm + 3840;          // 32*296 floats

    const int b   = blockIdx.z;
    const int gy0 = blockIdx.y * 8;
    const int gx0 = blockIdx.x * 8;
    const int tid = threadIdx.x;
    const int wid = tid >> 5, lane = tid & 31;
    const int ct = wid & 1, nq = wid >> 1;
    const int lg = lane >> 2, lt = lane & 3;
    const int co0 = ct*16;

    float C[2][4];
#pragma unroll
    for (int i = 0; i < 2; i++)
#pragma unroll
        for (int j = 0; j < 4; j++) C[i][j] = 0.f;

    for (int ch = 0; ch < 2; ch++) {
        const float* xb = xin + (size_t)(b*64 + ch*32)*4096;
        for (int e = tid; e < 3200; e += 256) {
            int ci = e / 100, rem = e % 100;
            int r = rem / 10, c = rem % 10;
            int gy = gy0 - 1 + r, gx = gx0 - 1 + c;
            float val = 0.f;
            if ((unsigned)gy < 64u && (unsigned)gx < 64u)
                val = xb[ci*4096 + gy*64 + gx];
            x_s[(ci*10 + r)*12 + c] = to_tf32(val);
        }
        for (int e = tid; e < 9216; e += 256) {
            int co = e / 288, rem = e % 288;
            int ci = rem / 9, tap = rem % 9;
            w_s[ci*WSTR + co*9 + tap] = to_tf32(w[(co*64 + ch*32 + ci)*9 + tap]);
        }
        __syncthreads();

#pragma unroll
        for (int cc = 0; cc < 4; cc++) {
            const int ci0 = cc*8;
            uint32_t a[9][4];
#pragma unroll
            for (int tap = 0; tap < 9; tap++) {
                a[tap][0] = __float_as_uint(w_s[(ci0 + lt)*WSTR + (co0 + lg)*9 + tap]);
                a[tap][1] = __float_as_uint(w_s[(ci0 + lt)*WSTR + (co0 + 8 + lg)*9 + tap]);
                a[tap][2] = __float_as_uint(w_s[(ci0 + 4 + lt)*WSTR + (co0 + lg)*9 + tap]);
                a[tap][3] = __float_as_uint(w_s[(ci0 + 4 + lt)*WSTR + (co0 + 8 + lg)*9 + tap]);
            }
#pragma unroll
            for (int nt = 0; nt < 2; nt++) {
                const int py = nq*2 + nt;
#pragma unroll
                for (int tap = 0; tap < 9; tap++) {
                    const int dy = tap / 3, dx = tap % 3;
                    const int colb = (py + dy)*12 + dx + lg;
                    uint32_t b0 = __float_as_uint(x_s[(ci0 + lt)*120 + colb]);
                    uint32_t b1 = __float_as_uint(x_s[(ci0 + 4 + lt)*120 + colb]);
                    mma_tf32(C[nt], a[tap][0], a[tap][1], a[tap][2], a[tap][3], b0, b1);
                }
            }
        }
        __syncthreads();
    }

#pragma unroll
    for (int nt = 0; nt < 2; nt++) {
        const int py = nq*2 + nt;
#pragma unroll
        for (int h = 0; h < 2; h++) {
            int co = co0 + h*8 + lg;
            float scale = bg[co] * rsqrtf(bv[co] + 1e-5f);
            float shift = bb[co] - bm[co]*scale;
            float2 v;
            v.x = silu_f(C[nt][2*h]  *scale + shift);
            v.y = silu_f(C[nt][2*h+1]*scale + shift);
            *reinterpret_cast<float2*>(out + (((size_t)(b*32 + co)*64 + gy0 + py)*64 + gx0 + 2*lt)) = v;
        }
    }
}

// ======== conv2 (tf32 TC, 16x8 tile, grid 128) + fused QKV — R11 exact ========
__global__ void __launch_bounds__(256) conv2_qkv_kernel(
        const float* __restrict__ xin, const float* __restrict__ w,
        const float* __restrict__ bg, const float* __restrict__ bb,
        const float* __restrict__ bm, const float* __restrict__ bv,
        const float* __restrict__ q_w, const float* __restrict__ q_b,
        const float* __restrict__ k_w, const float* __restrict__ k_b,
        const float* __restrict__ v_w, const float* __restrict__ v_b,
        float* __restrict__ out,
        float* __restrict__ gqo, float* __restrict__ gko, float* __restrict__ gvo) {
    constexpr int COUT = 64;
    extern __shared__ __align__(16) float sm[];
    float* x_s = sm;                // [32][10][20]
    float* w_s = sm + 6400;         // [ci 32][co 64][12]
    float* y_t  = sm;               // overlay [128][65]
    float* wq_s = sm + 8320;        // [64][80]
    float* qb_s = sm + 8320 + 5120; // [80]

    const int b   = blockIdx.z;
    const int gy0 = blockIdx.y * 8;
    const int gx0 = blockIdx.x * 16;
    const int tid = threadIdx.x;
    const int wid = tid >> 5, lane = tid & 31;
    const int ct = wid & 3, nh = wid >> 2;
    const int lg = lane >> 2, lt = lane & 3;

    float C[8][4];
#pragma unroll
    for (int i = 0; i < 8; i++)
#pragma unroll
        for (int j = 0; j < 4; j++) C[i][j] = 0.f;

    {
        const float* xb = xin + (size_t)(b*32)*4096;
        for (int e = tid; e < 32*10*18; e += 256) {
            int ci = e / 180; int rem = e % 180;
            int r = rem / 18, c = rem % 18;
            int gy = gy0 - 1 + r, gx = gx0 - 1 + c;
            float val = 0.f;
            if ((unsigned)gy < 64u && (unsigned)gx < 64u)
                val = xb[ci*4096 + gy*64 + gx];
            x_s[(ci*10 + r)*20 + c] = to_tf32(val);
        }
        for (int e = tid; e < 64*32*9; e += 256) {
            int co = e / 288, rem = e % 288;
            int ci = rem / 9, tap = rem % 9;
            w_s[(ci*64 + co)*12 + tap] = to_tf32(w[e]);
        }
        __syncthreads();

#pragma unroll
        for (int cc = 0; cc < 4; cc++) {
            const int ci0 = cc*8;
            uint32_t a[9][4];
            const int co0 = ct*16;
#pragma unroll
            for (int tap = 0; tap < 9; tap++) {
                a[tap][0] = __float_as_uint(w_s[((ci0 + lt)*64 + co0 + lg)*12 + tap]);
                a[tap][1] = __float_as_uint(w_s[((ci0 + lt)*64 + co0 + 8 + lg)*12 + tap]);
                a[tap][2] = __float_as_uint(w_s[((ci0 + 4 + lt)*64 + co0 + lg)*12 + tap]);
                a[tap][3] = __float_as_uint(w_s[((ci0 + 4 + lt)*64 + co0 + 8 + lg)*12 + tap]);
            }
#pragma unroll
            for (int nt = 0; nt < 8; nt++) {
                const int n0 = (nh*8 + nt)*8;
                const int py = n0 >> 4, px0 = n0 & 15;
#pragma unroll
                for (int tap = 0; tap < 9; tap++) {
                    const int dy = tap / 3, dx = tap % 3;
                    const int colb = (py + dy)*20 + px0 + dx + lg;
                    uint32_t b0 = __float_as_uint(x_s[(ci0 + lt)*200 + colb]);
                    uint32_t b1 = __float_as_uint(x_s[(ci0 + 4 + lt)*200 + colb]);
                    mma_tf32(C[nt], a[tap][0], a[tap][1], a[tap][2], a[tap][3], b0, b1);
                }
            }
        }
        __syncthreads();
    }

#pragma unroll
    for (int nt = 0; nt < 8; nt++) {
        const int n0 = (nh*8 + nt)*8;
        const int py = n0 >> 4;
        const int px = (n0 & 15) + 2*lt;
#pragma unroll
        for (int h = 0; h < 2; h++) {
            int co = ct*16 + h*8 + lg;
            float scale = bg[co] * rsqrtf(bv[co] + 1e-5f);
            float shift = bb[co] - bm[co]*scale;
            float v0 = silu_f(C[nt][2*h]  *scale + shift);
            float v1 = silu_f(C[nt][2*h+1]*scale + shift);
            *reinterpret_cast<float2*>(out + (((size_t)(b*COUT + co)*64 + gy0 + py)*64 + gx0 + px)) =
                make_float2(v0, v1);
            y_t[(py*16 + px)*65 + co]     = v0;
            y_t[(py*16 + px + 1)*65 + co] = v1;
        }
    }
    for (int e = tid; e < 5120; e += 256) {
        int c = e / 80, o = e % 80;
        float val;
        if (o < 8)       val = q_w[o*64 + c];
        else if (o < 16) val = k_w[(o-8)*64 + c];
        else             val = v_w[(o-16)*64 + c];
        wq_s[c*80 + o] = val;
    }
    if (tid < 80) {
        float val;
        if (tid < 8)       val = q_b[tid];
        else if (tid < 16) val = k_b[tid-8];
        else               val = v_b[tid-16];
        qb_s[tid] = val;
    }
    __syncthreads();

    const int px   = tid >> 1;
    const int half = tid & 1;
    float a2[40];
    const float* bb2 = qb_s + half*40;
#pragma unroll
    for (int j = 0; j < 40; j++) a2[j] = bb2[j];
    for (int c = 0; c < 64; c++) {
        float yv = y_t[px*65 + c];
        const float4* wp = reinterpret_cast<const float4*>(wq_s + c*80 + half*40);
#pragma unroll
        for (int j4 = 0; j4 < 10; j4++) {
            float4 w4 = wp[j4];
            a2[j4*4+0] = fmaf(w4.x, yv, a2[j4*4+0]);
            a2[j4*4+1] = fmaf(w4.y, yv, a2[j4*4+1]);
            a2[j4*4+2] = fmaf(w4.z, yv, a2[j4*4+2]);
            a2[j4*4+3] = fmaf(w4.w, yv, a2[j4*4+3]);
        }
    }
    const int n = (gy0 + (px >> 4))*64 + gx0 + (px & 15);
    if (half == 0) {
        float4* qd = reinterpret_cast<float4*>(gqo + (size_t)(b*4096 + n)*8);
        qd[0] = make_float4(a2[0], a2[1], a2[2],  a2[3]);
        qd[1] = make_float4(a2[4], a2[5], a2[6],  a2[7]);
        float4* kd = reinterpret_cast<float4*>(gko + (size_t)(b*4096 + n)*8);
        kd[0] = make_float4(a2[8],  a2[9],  a2[10], a2[11]);
        kd[1] = make_float4(a2[12], a2[13], a2[14], a2[15]);
        float4* vd = reinterpret_cast<float4*>(gvo + (size_t)(b*4096 + n)*64);
#pragma unroll
        for (int j = 0; j < 6; j++)
            vd[j] = make_float4(a2[16+4*j], a2[17+4*j], a2[18+4*j], a2[19+4*j]);
    } else {
        float* vd = gvo + (size_t)(b*4096 + n)*64 + 24;
#pragma unroll
        for (int j = 0; j < 10; j++)
            *reinterpret_cast<float4*>(vd + 4*j) =
                make_float4(a2[4*j], a2[1+4*j], a2[2+4*j], a2[3+4*j]);
    }
}

// ---------------- flash attention, 512 threads / 16 warps (key-split) ----------------
// Warp pair (w, w+8): same 16 q-rows; khalf=w>>3 selects key half of every tile.
// Per warp per tile: 8 QK mmas, 32 exps, 4 PV ksteps. Partials merged once at end.
__device__ __forceinline__ void ld_ktile(const float* kb, int kt, int tid, float2& kv) {
    int key = tid >> 2, h = tid & 3;
    kv = *reinterpret_cast<const float2*>(kb + (size_t)(kt*128 + key)*8 + h*2);
}
__device__ __forceinline__ void st_ktile(unsigned char* K_s, int tid, const float2& kv) {
    int key = tid >> 2, h = tid & 3;
    *reinterpret_cast<uint32_t*>(K_s + key*16 + h*4) = f2bf2(kv.x, kv.y);
}
__device__ __forceinline__ void ld_vtile(const float* vb, int kt, int tid,
                                         float4* va, float4* vb2) {
#pragma unroll
    for (int it = 0; it < 2; it++) {
        int id = it*512 + tid;
        int kp = id >> 4, c4 = id & 15;
        const float4* vr = reinterpret_cast<const float4*>(vb + (size_t)(kt*128 + 2*kp)*64) + c4;
        va[it]  = vr[0];
        vb2[it] = vr[16];
    }
}
__device__ __forceinline__ void st_vtile(unsigned char* VT_s, int tid,
                                         const float4* va, const float4* vb2) {
#pragma unroll
    for (int it = 0; it < 2; it++) {
        int id = it*512 + tid;
        int kp = id >> 4, c4 = id & 15;
#pragma unroll
        for (int i = 0; i < 4; i++) {
            int ch = c4*4 + i;
            float lo = (i==0)?va[it].x :(i==1)?va[it].y :(i==2)?va[it].z :va[it].w;
            float hi = (i==0)?vb2[it].x:(i==1)?vb2[it].y:(i==2)?vb2[it].z:vb2[it].w;
            uint32_t byte = (uint32_t)(ch*272 + ((((kp>>2) ^ (ch>>3)) & 15) << 4) + (kp & 3)*4);
            *reinterpret_cast<uint32_t*>(VT_s + byte) = f2bf2(lo, hi);
        }
    }
}

__global__ void __launch_bounds__(512, 1) flash_hmma_kernel(
        const float* __restrict__ gq,
        const float* __restrict__ gk,
        const float* __restrict__ gv,
        const float* __restrict__ x,
        const float* __restrict__ gy,
        const float* __restrict__ gamma,
        float* __restrict__ outp) {
    __shared__ __align__(128) unsigned char smem_all[2*2048 + 2*17408];  // 38912B
    unsigned char* K_s0  = smem_all;
    unsigned char* K_s1  = smem_all + 2048;
    unsigned char* VT_s0 = smem_all + 4096;
    unsigned char* VT_s1 = smem_all + 4096 + 17408;
    const uint32_t VT_su0 = smem_u32(VT_s0);
    const uint32_t VT_su1 = smem_u32(VT_s1);
    float* m_o  = reinterpret_cast<float*>(smem_all);          // merge: [8][32][32] = 32768B
    float* m_rs = reinterpret_cast<float*>(smem_all + 32768);  // merge: [8][32][2]  = 2048B
    float* t_s  = reinterpret_cast<float*>(smem_all);          // transpose overlay [128][66]

    const int b    = blockIdx.y;
    const int qt   = blockIdx.x;
    const int tid  = threadIdx.x;
    const int wid  = tid >> 5;
    const int lane = tid & 31;
    const int rw    = wid & 7;      // row-group 0..7 (16 q-rows each)
    const int khalf = wid >> 3;     // key half 0/1
    const int g    = lane >> 2;
    const int t    = lane & 3;

    const int qrow = b*4096 + qt*128 + rw*16 + g;
    float2 q0 = *reinterpret_cast<const float2*>(gq + (size_t)qrow*8 + 2*t);
    float2 q1 = *reinterpret_cast<const float2*>(gq + (size_t)(qrow+8)*8 + 2*t);
    const uint32_t qa0 = f2bf2(q0.x, q0.y);
    const uint32_t qa1 = f2bf2(q1.x, q1.y);

    float o[8][4];
#pragma unroll
    for (int i = 0; i < 8; i++)
#pragma unroll
        for (int j = 0; j < 4; j++) o[i][j] = 0.f;
    float rs0 = 0.f, rs1 = 0.f;

    const float* kb = gk + (size_t)b*4096*8;
    const float* vb = gv + (size_t)b*4096*64;

    const int sel  = lane >> 3;
    const int l8   = lane & 7;
    const int ch_off    = ((sel >> 1) << 3) + l8;
    const int chunk_off = sel & 1;

    float2 kv_pf; float4 va_pf[2], vb_pf[2];
    ld_ktile(kb, 0, tid, kv_pf);
    ld_vtile(vb, 0, tid, va_pf, vb_pf);
    st_ktile(K_s0, tid, kv_pf);
    st_vtile(VT_s0, tid, va_pf, vb_pf);
    __syncthreads();

    for (int kt = 0; kt < 32; kt++) {
        const int cur = kt & 1;
        const uint32_t vbase = cur ? VT_su1 : VT_su0;
        unsigned char* Kc = cur ? K_s1 : K_s0;

        if (kt < 31) {
            ld_ktile(kb, kt+1, tid, kv_pf);
            ld_vtile(vb, kt+1, tid, va_pf, vb_pf);
        }

        // ---- QK: this warp's 8 key-subtiles ----
        float e[8][4];
#pragma unroll
        for (int nt = 0; nt < 8; nt++) {
            int ntg = khalf*8 + nt;
            uint32_t kb32 = *reinterpret_cast<const uint32_t*>(Kc + ntg*128 + lane*4);
            float d0 = 0.f, d1 = 0.f, d2 = 0.f, d3 = 0.f;
            asm volatile(
                "mma.sync.aligned.m16n8k8.row.col.f32.bf16.bf16.f32 "
                "{%0,%1,%2,%3}, {%4,%5}, {%6}, {%0,%1,%2,%3};"
                : "+f"(d0), "+f"(d1), "+f"(d2), "+f"(d3)
                : "r"(qa0), "r"(qa1), "r"(kb32));
            e[nt][0] = d0; e[nt][1] = d1; e[nt][2] = d2; e[nt][3] = d3;
        }
#pragma unroll
        for (int nt = 0; nt < 8; nt++) {
            e[nt][0] = __expf(e[nt][0]);
            e[nt][1] = __expf(e[nt][1]);
            e[nt][2] = __expf(e[nt][2]);
            e[nt][3] = __expf(e[nt][3]);
            rs0 += e[nt][0] + e[nt][1];
            rs1 += e[nt][2] + e[nt][3];
        }

        if (kt < 31) {
            st_ktile(cur ? K_s0 : K_s1, tid, kv_pf);
            st_vtile(cur ? VT_s0 : VT_s1, tid, va_pf, vb_pf);
        }

        // ---- PV: this warp's 4 ksteps ----
#pragma unroll
        for (int ksl = 0; ksl < 4; ksl++) {
            int ks = khalf*4 + ksl;
            uint32_t a0 = f2bf2(e[2*ksl][0],   e[2*ksl][1]);
            uint32_t a1 = f2bf2(e[2*ksl][2],   e[2*ksl][3]);
            uint32_t a2 = f2bf2(e[2*ksl+1][0], e[2*ksl+1][1]);
            uint32_t a3 = f2bf2(e[2*ksl+1][2], e[2*ksl+1][3]);
            int chunk = 2*ks + chunk_off;
#pragma unroll
            for (int nt2 = 0; nt2 < 4; nt2++) {
                int ch = nt2*16 + ch_off;
                uint32_t addr = vbase + (uint32_t)(ch*272 + (((chunk ^ (ch>>3)) & 15) << 4));
                uint32_t b0, b1, b2, b3;
                asm volatile(
                    "ldmatrix.sync.aligned.m8n8.x4.shared.b16 {%0,%1,%2,%3}, [%4];"
                    : "=r"(b0), "=r"(b1), "=r"(b2), "=r"(b3) : "r"(addr));
                asm volatile(
                    "mma.sync.aligned.m16n8k16.row.col.f32.bf16.bf16.f32 "
                    "{%0,%1,%2,%3}, {%4,%5,%6,%7}, {%8,%9}, {%0,%1,%2,%3};"
                    : "+f"(o[nt2*2][0]), "+f"(o[nt2*2][1]), "+f"(o[nt2*2][2]), "+f"(o[nt2*2][3])
                    : "r"(a0), "r"(a1), "r"(a2), "r"(a3), "r"(b0), "r"(b1));
                asm volatile(
                    "mma.sync.aligned.m16n8k16.row.col.f32.bf16.bf16.f32 "
                    "{%0,%1,%2,%3}, {%4,%5,%6,%7}, {%8,%9}, {%0,%1,%2,%3};"
                    : "+f"(o[nt2*2+1][0]), "+f"(o[nt2*2+1][1]), "+f"(o[nt2*2+1][2]), "+f"(o[nt2*2+1][3])
                    : "r"(a0), "r"(a1), "r"(a2), "r"(a3), "r"(b2), "r"(b3));
            }
        }
        __syncthreads();
    }

    // ---- reduce row sums within quad ----
    rs0 += __shfl_xor_sync(0xffffffffu, rs0, 1);
    rs0 += __shfl_xor_sync(0xffffffffu, rs0, 2);
    rs1 += __shfl_xor_sync(0xffffffffu, rs1, 1);
    rs1 += __shfl_xor_sync(0xffffffffu, rs1, 2);

    // ---- merge key halves: khalf=1 stores partials, khalf=0 adds ----
    if (khalf == 1) {
        float* dst = m_o + (rw*32 + lane)*32;
#pragma unroll
        for (int i = 0; i < 8; i++)
#pragma unroll
            for (int j = 0; j < 4; j++) dst[i*4 + j] = o[i][j];
        m_rs[(rw*32 + lane)*2 + 0] = rs0;
        m_rs[(rw*32 + lane)*2 + 1] = rs1;
    }
    __syncthreads();
    if (khalf == 0) {
        const float* src = m_o + (rw*32 + lane)*32;
#pragma unroll
        for (int i = 0; i < 8; i++)
#pragma unroll
            for (int j = 0; j < 4; j++) o[i][j] += src[i*4 + j];
        rs0 += m_rs[(rw*32 + lane)*2 + 0];
        rs1 += m_rs[(rw*32 + lane)*2 + 1];
    }
    __syncthreads();   // merge reads done; t_s overlay safe

    // ---- khalf=0 warps: normalize + transpose to smem ----
    if (khalf == 0) {
        const float inv0 = 1.0f / rs0, inv1 = 1.0f / rs1;
        const int r0 = rw*16 + g;
#pragma unroll
        for (int nt = 0; nt < 8; nt++) {
            int ch = nt*8 + 2*t;
            *reinterpret_cast<float2*>(t_s + r0*66 + ch) =
                make_float2(o[nt][0]*inv0, o[nt][1]*inv0);
            *reinterpret_cast<float2*>(t_s + (r0+8)*66 + ch) =
                make_float2(o[nt][2]*inv1, o[nt][3]*inv1);
        }
    }
    __syncthreads();

    // ---- all 512 threads: out = x + 2y + 2*gamma*attn ----
    const float g2 = 2.0f * gamma[0];
    const int c  = tid >> 3;           // 0..63
    const int i0 = (tid & 7) * 16;     // 0..112 step 16
    const size_t base = ((size_t)(b*64 + c))*4096 + qt*128 + i0;
#pragma unroll
    for (int i4 = 0; i4 < 4; i4++) {
        float4 xv = *reinterpret_cast<const float4*>(x  + base + i4*4);
        float4 yv = *reinterpret_cast<const float4*>(gy + base + i4*4);
        float4 ov;
        ov.x = xv.x + 2.f*yv.x + g2*t_s[(i0 + i4*4 + 0)*66 + c];
        ov.y = xv.y + 2.f*yv.y + g2*t_s[(i0 + i4*4 + 1)*66 + c];
        ov.z = xv.z + 2.f*yv.z + g2*t_s[(i0 + i4*4 + 2)*66 + c];
        ov.w = xv.w + 2.f*yv.w + g2*t_s[(i0 + i4*4 + 3)*66 + c];
        *reinterpret_cast<float4*>(outp + base + i4*4) = ov;
    }
}

// ---------------- launch ----------------
extern "C" void kernel_launch(void* const* d_in, const int* in_sizes, int n_in,
                              void* d_out, int out_size) {
    const float* x     = (const float*)d_in[0];
    const float* cv1_w = (const float*)d_in[1];
    const float* bn1_g = (const float*)d_in[2];
    const float* bn1_b = (const float*)d_in[3];
    const float* bn1_m = (const float*)d_in[4];
    const float* bn1_v = (const float*)d_in[5];
    const float* cv2_w = (const float*)d_in[6];
    const float* bn2_g = (const float*)d_in[7];
    const float* bn2_b = (const float*)d_in[8];
    const float* bn2_m = (const float*)d_in[9];
    const float* bn2_v = (const float*)d_in[10];
    const float* q_w   = (const float*)d_in[11];
    const float* q_b   = (const float*)d_in[12];
    const float* k_w   = (const float*)d_in[13];
    const float* k_b   = (const float*)d_in[14];
    const float* v_w   = (const float*)d_in[15];
    const float* v_b   = (const float*)d_in[16];
    const float* gamma = (const float*)d_in[17];
    float* out = (float*)d_out;

    void *py1, *py, *pq, *pk, *pv;
    cudaGetSymbolAddress(&py1, g_y1);
    cudaGetSymbolAddress(&py,  g_y);
    cudaGetSymbolAddress(&pq,  g_q);
    cudaGetSymbolAddress(&pk,  g_k);
    cudaGetSymbolAddress(&pv,  g_v);

    const int SMEM_C1 = (3840 + 32*296) * 4;     // 53248
    const int SMEM_C2 = (6400 + 32*64*12) * 4;   // 123904

    cudaFuncSetAttribute(conv1_kernel, cudaFuncAttributeMaxDynamicSharedMemorySize, SMEM_C1);
    cudaFuncSetAttribute(conv2_qkv_kernel, cudaFuncAttributeMaxDynamicSharedMemorySize, SMEM_C2);

    conv1_kernel<<<dim3(8,8,4), 256, SMEM_C1>>>(
        x, cv1_w, bn1_g, bn1_b, bn1_m, bn1_v, (float*)py1);
    conv2_qkv_kernel<<<dim3(4,8,4), 256, SMEM_C2>>>(
        (const float*)py1, cv2_w, bn2_g, bn2_b, bn2_m, bn2_v,
        q_w, q_b, k_w, k_b, v_w, v_b,
        (float*)py, (float*)pq, (float*)pk, (float*)pv);
    flash_hmma_kernel<<<dim3(32,4), 512>>>(
        (const float*)pq, (const float*)pk, (const float*)pv,
        x, (const float*)py, gamma, out);
}

// round 14
// speedup vs baseline: 1.1147x; 1.1147x over previous
#include <cuda_runtime.h>
#include <cstdint>

// ---------------- scratch (device globals; no allocation allowed) ----------------
__device__ float    g_y1[4*32*64*64];    // cv1 output
__device__ float    g_y [4*64*64*64];    // cv2 output
__device__ uint32_t g_q [4*4096*4];      // q[b][n][8] bf16x2-packed
__device__ uint32_t g_k [4*4096*4];      // k[b][n][8] bf16x2-packed
__device__ uint32_t g_vt[4*64*2048];     // v^T [b][ch][n/2] bf16x2-packed

__device__ __forceinline__ float silu_f(float t) {
    return t * (1.0f / (1.0f + __expf(-t)));
}
__device__ __forceinline__ uint32_t f2bf2(float lo, float hi) {
    uint32_t r;
    asm("cvt.rn.bf16x2.f32 %0, %1, %2;" : "=r"(r) : "f"(hi), "f"(lo));
    return r;
}
__device__ __forceinline__ uint16_t bf16b(float v) {
    return (uint16_t)(f2bf2(v, 0.f) & 0xffffu);
}
__device__ __forceinline__ uint32_t smem_u32(const void* p) {
    uint32_t a;
    asm("{ .reg .u64 t; cvta.to.shared.u64 t, %1; cvt.u32.u64 %0, t; }" : "=r"(a) : "l"(p));
    return a;
}
__device__ __forceinline__ float to_tf32(float x) {
    uint32_t r;
    asm("cvt.rna.tf32.f32 %0, %1;" : "=r"(r) : "f"(x));
    return __uint_as_float(r);
}
__device__ __forceinline__ void mma_tf32(float c[4], uint32_t a0, uint32_t a1,
                                         uint32_t a2, uint32_t a3,
                                         uint32_t b0, uint32_t b1) {
    asm volatile(
        "mma.sync.aligned.m16n8k8.row.col.f32.tf32.tf32.f32 "
        "{%0,%1,%2,%3}, {%4,%5,%6,%7}, {%8,%9}, {%0,%1,%2,%3};"
        : "+f"(c[0]), "+f"(c[1]), "+f"(c[2]), "+f"(c[3])
        : "r"(a0), "r"(a1), "r"(a2), "r"(a3), "r"(b0), "r"(b1));
}
__device__ __forceinline__ void cp16(uint32_t smem_dst, const void* gsrc) {
    asm volatile("cp.async.cg.shared.global [%0], [%1], 16;"
                 :: "r"(smem_dst), "l"(gsrc) : "memory");
}

// ======== conv1: 3x3+BN+SiLU tf32 TC, 8x8 tile, grid 256 (R11 exact) ========
__global__ void __launch_bounds__(256, 2) conv1_kernel(
        const float* __restrict__ xin, const float* __restrict__ w,
        const float* __restrict__ bg, const float* __restrict__ bb,
        const float* __restrict__ bm, const float* __restrict__ bv,
        float* __restrict__ out) {
    constexpr int WSTR = 32*9 + 8;   // 296
    extern __shared__ __align__(16) float sm[];
    float* x_s = sm;                 // 3840 floats
    float* w_s = sm + 3840;          // 32*296 floats

    const int b   = blockIdx.z;
    const int gy0 = blockIdx.y * 8;
    const int gx0 = blockIdx.x * 8;
    const int tid = threadIdx.x;
    const int wid = tid >> 5, lane = tid & 31;
    const int ct = wid & 1, nq = wid >> 1;
    const int lg = lane >> 2, lt = lane & 3;
    const int co0 = ct*16;

    float C[2][4];
#pragma unroll
    for (int i = 0; i < 2; i++)
#pragma unroll
        for (int j = 0; j < 4; j++) C[i][j] = 0.f;

    for (int ch = 0; ch < 2; ch++) {
        const float* xb = xin + (size_t)(b*64 + ch*32)*4096;
        for (int e = tid; e < 3200; e += 256) {
            int ci = e / 100, rem = e % 100;
            int r = rem / 10, c = rem % 10;
            int gy = gy0 - 1 + r, gx = gx0 - 1 + c;
            float val = 0.f;
            if ((unsigned)gy < 64u && (unsigned)gx < 64u)
                val = xb[ci*4096 + gy*64 + gx];
            x_s[(ci*10 + r)*12 + c] = to_tf32(val);
        }
        for (int e = tid; e < 9216; e += 256) {
            int co = e / 288, rem = e % 288;
            int ci = rem / 9, tap = rem % 9;
            w_s[ci*WSTR + co*9 + tap] = to_tf32(w[(co*64 + ch*32 + ci)*9 + tap]);
        }
        __syncthreads();

#pragma unroll
        for (int cc = 0; cc < 4; cc++) {
            const int ci0 = cc*8;
            uint32_t a[9][4];
#pragma unroll
            for (int tap = 0; tap < 9; tap++) {
                a[tap][0] = __float_as_uint(w_s[(ci0 + lt)*WSTR + (co0 + lg)*9 + tap]);
                a[tap][1] = __float_as_uint(w_s[(ci0 + lt)*WSTR + (co0 + 8 + lg)*9 + tap]);
                a[tap][2] = __float_as_uint(w_s[(ci0 + 4 + lt)*WSTR + (co0 + lg)*9 + tap]);
                a[tap][3] = __float_as_uint(w_s[(ci0 + 4 + lt)*WSTR + (co0 + 8 + lg)*9 + tap]);
            }
#pragma unroll
            for (int nt = 0; nt < 2; nt++) {
                const int py = nq*2 + nt;
#pragma unroll
                for (int tap = 0; tap < 9; tap++) {
                    const int dy = tap / 3, dx = tap % 3;
                    const int colb = (py + dy)*12 + dx + lg;
                    uint32_t b0 = __float_as_uint(x_s[(ci0 + lt)*120 + colb]);
                    uint32_t b1 = __float_as_uint(x_s[(ci0 + 4 + lt)*120 + colb]);
                    mma_tf32(C[nt], a[tap][0], a[tap][1], a[tap][2], a[tap][3], b0, b1);
                }
            }
        }
        __syncthreads();
    }

#pragma unroll
    for (int nt = 0; nt < 2; nt++) {
        const int py = nq*2 + nt;
#pragma unroll
        for (int h = 0; h < 2; h++) {
            int co = co0 + h*8 + lg;
            float scale = bg[co] * rsqrtf(bv[co] + 1e-5f);
            float shift = bb[co] - bm[co]*scale;
            float2 v;
            v.x = silu_f(C[nt][2*h]  *scale + shift);
            v.y = silu_f(C[nt][2*h+1]*scale + shift);
            *reinterpret_cast<float2*>(out + (((size_t)(b*32 + co)*64 + gy0 + py)*64 + gx0 + 2*lt)) = v;
        }
    }
}

// ======== conv2 (tf32 TC, 16x8 tile, grid 128) + fused QKV (bf16 out, v^T) ========
__global__ void __launch_bounds__(256) conv2_qkv_kernel(
        const float* __restrict__ xin, const float* __restrict__ w,
        const float* __restrict__ bg, const float* __restrict__ bb,
        const float* __restrict__ bm, const float* __restrict__ bv,
        const float* __restrict__ q_w, const float* __restrict__ q_b,
        const float* __restrict__ k_w, const float* __restrict__ k_b,
        const float* __restrict__ v_w, const float* __restrict__ v_b,
        float* __restrict__ out,
        uint32_t* __restrict__ gqo, uint32_t* __restrict__ gko,
        uint32_t* __restrict__ gvt) {
    constexpr int COUT = 64;
    extern __shared__ __align__(16) float sm[];
    float* x_s = sm;                // [32][10][20]
    float* w_s = sm + 6400;         // [ci 32][co 64][12]
    // phase-2 overlay:
    float* y_t  = sm;               // [128][65] = 8320 floats
    float* wq_s = sm + 8320;        // [64][80]
    float* qb_s = sm + 8320 + 5120; // [80]
    uint16_t* v_sm = reinterpret_cast<uint16_t*>(sm + 13520);  // [64ch][128px] bf16 (16KB)

    const int b   = blockIdx.z;
    const int gy0 = blockIdx.y * 8;
    const int gx0 = blockIdx.x * 16;
    const int tid = threadIdx.x;
    const int wid = tid >> 5, lane = tid & 31;
    const int ct = wid & 3, nh = wid >> 2;
    const int lg = lane >> 2, lt = lane & 3;

    float C[8][4];
#pragma unroll
    for (int i = 0; i < 8; i++)
#pragma unroll
        for (int j = 0; j < 4; j++) C[i][j] = 0.f;

    {
        const float* xb = xin + (size_t)(b*32)*4096;
        for (int e = tid; e < 32*10*18; e += 256) {
            int ci = e / 180; int rem = e % 180;
            int r = rem / 18, c = rem % 18;
            int gy = gy0 - 1 + r, gx = gx0 - 1 + c;
            float val = 0.f;
            if ((unsigned)gy < 64u && (unsigned)gx < 64u)
                val = xb[ci*4096 + gy*64 + gx];
            x_s[(ci*10 + r)*20 + c] = to_tf32(val);
        }
        for (int e = tid; e < 64*32*9; e += 256) {
            int co = e / 288, rem = e % 288;
            int ci = rem / 9, tap = rem % 9;
            w_s[(ci*64 + co)*12 + tap] = to_tf32(w[e]);
        }
        __syncthreads();

#pragma unroll
        for (int cc = 0; cc < 4; cc++) {
            const int ci0 = cc*8;
            uint32_t a[9][4];
            const int co0 = ct*16;
#pragma unroll
            for (int tap = 0; tap < 9; tap++) {
                a[tap][0] = __float_as_uint(w_s[((ci0 + lt)*64 + co0 + lg)*12 + tap]);
                a[tap][1] = __float_as_uint(w_s[((ci0 + lt)*64 + co0 + 8 + lg)*12 + tap]);
                a[tap][2] = __float_as_uint(w_s[((ci0 + 4 + lt)*64 + co0 + lg)*12 + tap]);
                a[tap][3] = __float_as_uint(w_s[((ci0 + 4 + lt)*64 + co0 + 8 + lg)*12 + tap]);
            }
#pragma unroll
            for (int nt = 0; nt < 8; nt++) {
                const int n0 = (nh*8 + nt)*8;
                const int py = n0 >> 4, px0 = n0 & 15;
#pragma unroll
                for (int tap = 0; tap < 9; tap++) {
                    const int dy = tap / 3, dx = tap % 3;
                    const int colb = (py + dy)*20 + px0 + dx + lg;
                    uint32_t b0 = __float_as_uint(x_s[(ci0 + lt)*200 + colb]);
                    uint32_t b1 = __float_as_uint(x_s[(ci0 + 4 + lt)*200 + colb]);
                    mma_tf32(C[nt], a[tap][0], a[tap][1], a[tap][2], a[tap][3], b0, b1);
                }
            }
        }
        __syncthreads();
    }

    // epilogue: BN + SiLU -> gmem y AND smem y_t[px][co]
#pragma unroll
    for (int nt = 0; nt < 8; nt++) {
        const int n0 = (nh*8 + nt)*8;
        const int py = n0 >> 4;
        const int px = (n0 & 15) + 2*lt;
#pragma unroll
        for (int h = 0; h < 2; h++) {
            int co = ct*16 + h*8 + lg;
            float scale = bg[co] * rsqrtf(bv[co] + 1e-5f);
            float shift = bb[co] - bm[co]*scale;
            float v0 = silu_f(C[nt][2*h]  *scale + shift);
            float v1 = silu_f(C[nt][2*h+1]*scale + shift);
            *reinterpret_cast<float2*>(out + (((size_t)(b*COUT + co)*64 + gy0 + py)*64 + gx0 + px)) =
                make_float2(v0, v1);
            y_t[(py*16 + px)*65 + co]     = v0;
            y_t[(py*16 + px + 1)*65 + co] = v1;
        }
    }
    // qkv weights ([64][80] c-major) + biases
    for (int e = tid; e < 5120; e += 256) {
        int c = e / 80, o = e % 80;
        float val;
        if (o < 8)       val = q_w[o*64 + c];
        else if (o < 16) val = k_w[(o-8)*64 + c];
        else             val = v_w[(o-16)*64 + c];
        wq_s[c*80 + o] = val;
    }
    if (tid < 80) {
        float val;
        if (tid < 8)       val = q_b[tid];
        else if (tid < 16) val = k_b[tid-8];
        else               val = v_b[tid-16];
        qb_s[tid] = val;
    }
    __syncthreads();

    // qkv: 2 threads per pixel, 40 outputs each
    const int px   = tid >> 1;
    const int half = tid & 1;
    float a2[40];
    const float* bb2 = qb_s + half*40;
#pragma unroll
    for (int j = 0; j < 40; j++) a2[j] = bb2[j];
    for (int c = 0; c < 64; c++) {
        float yv = y_t[px*65 + c];
        const float4* wp = reinterpret_cast<const float4*>(wq_s + c*80 + half*40);
#pragma unroll
        for (int j4 = 0; j4 < 10; j4++) {
            float4 w4 = wp[j4];
            a2[j4*4+0] = fmaf(w4.x, yv, a2[j4*4+0]);
            a2[j4*4+1] = fmaf(w4.y, yv, a2[j4*4+1]);
            a2[j4*4+2] = fmaf(w4.z, yv, a2[j4*4+2]);
            a2[j4*4+3] = fmaf(w4.w, yv, a2[j4*4+3]);
        }
    }
    const int n = (gy0 + (px >> 4))*64 + gx0 + (px & 15);
    const size_t row = (size_t)(b*4096 + n);
    if (half == 0) {
        *reinterpret_cast<uint4*>(gqo + row*4) = make_uint4(
            f2bf2(a2[0], a2[1]), f2bf2(a2[2], a2[3]),
            f2bf2(a2[4], a2[5]), f2bf2(a2[6], a2[7]));
        *reinterpret_cast<uint4*>(gko + row*4) = make_uint4(
            f2bf2(a2[8],  a2[9]),  f2bf2(a2[10], a2[11]),
            f2bf2(a2[12], a2[13]), f2bf2(a2[14], a2[15]));
#pragma unroll
        for (int j = 0; j < 24; j++)
            v_sm[j*128 + px] = bf16b(a2[16 + j]);
    } else {
#pragma unroll
        for (int j = 0; j < 40; j++)
            v_sm[(24 + j)*128 + px] = bf16b(a2[j]);
    }
    __syncthreads();

    // coalesced v^T write: g_vt[b][ch][n/2] (token pairs, tokens consecutive in x)
    const uint32_t* v32 = reinterpret_cast<const uint32_t*>(v_sm);
    for (int i = tid; i < 4096; i += 256) {
        int chn = i >> 6, lp = i & 63;
        int np = (gy0 + (lp >> 3))*32 + (gx0 >> 1) + (lp & 7);
        gvt[((size_t)(b*64 + chn))*2048 + np] = v32[chn*64 + lp];
    }
}

// ---------------- flash attention: cp.async staging, 3-deep pipeline ----------------
// 256 threads / 8 warps (R11 structure). K_s copied verbatim from g_k (bf16 packed);
// VT_s copied from g_vt with the 16B-chunk XOR swizzle applied to dst addresses.
// V tile = 64 ch x 16 chunks of 16B = 1024 chunks; 4 per thread.
__global__ void __launch_bounds__(256, 1) flash_hmma_kernel(
        const uint32_t* __restrict__ gq,
        const uint32_t* __restrict__ gk,
        const uint32_t* __restrict__ gvt,
        const float* __restrict__ x,
        const float* __restrict__ gy,
        const float* __restrict__ gamma,
        float* __restrict__ outp) {
    extern __shared__ __align__(128) unsigned char smem_all[];
    // K bufs: 3 x 2048 @ 0; VT bufs: 3 x 17408 @ 6144. total 58368.
    const uint32_t smb = smem_u32(smem_all);
    float* t_s = reinterpret_cast<float*>(smem_all);   // epilogue overlay [128][66]

    const int b    = blockIdx.y;
    const int qt   = blockIdx.x;
    const int tid  = threadIdx.x;
    const int wid  = tid >> 5;
    const int lane = tid & 31;
    const int g    = lane >> 2;
    const int t    = lane & 3;

    const int qrow = b*4096 + qt*128 + wid*16 + g;
    const uint32_t qa0 = gq[(size_t)qrow*4 + t];
    const uint32_t qa1 = gq[(size_t)(qrow+8)*4 + t];

    float o[8][4];
#pragma unroll
    for (int i = 0; i < 8; i++)
#pragma unroll
        for (int j = 0; j < 4; j++) o[i][j] = 0.f;
    float rs0 = 0.f, rs1 = 0.f;

    const uint32_t* kb = gk + (size_t)b*4096*4;
    const uint32_t* vtb = gvt + (size_t)b*64*2048;

    const int sel  = lane >> 3;
    const int l8   = lane & 7;
    const int ch_off    = ((sel >> 1) << 3) + l8;
    const int chunk_off = sel & 1;

    auto issue_tile = [&](int kt, int buf) {
        if (tid < 128)
            cp16(smb + (uint32_t)(buf*2048) + tid*16,
                 kb + (size_t)(kt*128 + tid)*4);
        uint32_t vbase = smb + 6144u + (uint32_t)buf*17408u;
#pragma unroll
        for (int it = 0; it < 4; it++) {
            int c = it*256 + tid;            // 0..1023
            int ch = c >> 4, chunk = c & 15;
            cp16(vbase + (uint32_t)(ch*272 + (((chunk ^ (ch>>3)) & 15) << 4)),
                 vtb + (size_t)ch*2048 + kt*64 + chunk*4);
        }
        asm volatile("cp.async.commit_group;" ::: "memory");
    };

    issue_tile(0, 0);
    issue_tile(1, 1);

    for (int kt = 0; kt < 32; kt++) {
        const int cur = kt % 3;
        if (kt < 31) {
            asm volatile("cp.async.wait_group 1;" ::: "memory");
        } else {
            asm volatile("cp.async.wait_group 0;" ::: "memory");
        }
        __syncthreads();   // tile kt visible; buffer (kt+2)%3 free (its compute ended last iter)
        if (kt + 2 < 32)
            issue_tile(kt + 2, (kt + 2) % 3);

        const unsigned char* Kc = smem_all + cur*2048;
        const uint32_t vbase = smb + 6144u + (uint32_t)cur*17408u;

        // ---- QK ----
        float e[16][4];
#pragma unroll
        for (int nt = 0; nt < 16; nt++) {
            uint32_t kb32 = *reinterpret_cast<const uint32_t*>(Kc + nt*128 + lane*4);
            float d0 = 0.f, d1 = 0.f, d2 = 0.f, d3 = 0.f;
            asm volatile(
                "mma.sync.aligned.m16n8k8.row.col.f32.bf16.bf16.f32 "
                "{%0,%1,%2,%3}, {%4,%5}, {%6}, {%0,%1,%2,%3};"
                : "+f"(d0), "+f"(d1), "+f"(d2), "+f"(d3)
                : "r"(qa0), "r"(qa1), "r"(kb32));
            e[nt][0] = d0; e[nt][1] = d1; e[nt][2] = d2; e[nt][3] = d3;
        }
#pragma unroll
        for (int nt = 0; nt < 16; nt++) {
            e[nt][0] = __expf(e[nt][0]);
            e[nt][1] = __expf(e[nt][1]);
            e[nt][2] = __expf(e[nt][2]);
            e[nt][3] = __expf(e[nt][3]);
            rs0 += e[nt][0] + e[nt][1];
            rs1 += e[nt][2] + e[nt][3];
        }

        // ---- PV ----
#pragma unroll
        for (int ks = 0; ks < 8; ks++) {
            uint32_t a0 = f2bf2(e[2*ks][0],   e[2*ks][1]);
            uint32_t a1 = f2bf2(e[2*ks][2],   e[2*ks][3]);
            uint32_t a2 = f2bf2(e[2*ks+1][0], e[2*ks+1][1]);
            uint32_t a3 = f2bf2(e[2*ks+1][2], e[2*ks+1][3]);
            int chunk = 2*ks + chunk_off;
#pragma unroll
            for (int nt2 = 0; nt2 < 4; nt2++) {
                int ch = nt2*16 + ch_off;
                uint32_t addr = vbase + (uint32_t)(ch*272 + (((chunk ^ (ch>>3)) & 15) << 4));
                uint32_t b0, b1, b2, b3;
                asm volatile(
                    "ldmatrix.sync.aligned.m8n8.x4.shared.b16 {%0,%1,%2,%3}, [%4];"
                    : "=r"(b0), "=r"(b1), "=r"(b2), "=r"(b3) : "r"(addr));
                asm volatile(
                    "mma.sync.aligned.m16n8k16.row.col.f32.bf16.bf16.f32 "
                    "{%0,%1,%2,%3}, {%4,%5,%6,%7}, {%8,%9}, {%0,%1,%2,%3};"
                    : "+f"(o[nt2*2][0]), "+f"(o[nt2*2][1]), "+f"(o[nt2*2][2]), "+f"(o[nt2*2][3])
                    : "r"(a0), "r"(a1), "r"(a2), "r"(a3), "r"(b0), "r"(b1));
                asm volatile(
                    "mma.sync.aligned.m16n8k16.row.col.f32.bf16.bf16.f32 "
                    "{%0,%1,%2,%3}, {%4,%5,%6,%7}, {%8,%9}, {%0,%1,%2,%3};"
                    : "+f"(o[nt2*2+1][0]), "+f"(o[nt2*2+1][1]), "+f"(o[nt2*2+1][2]), "+f"(o[nt2*2+1][3])
                    : "r"(a0), "r"(a1), "r"(a2), "r"(a3), "r"(b2), "r"(b3));
            }
        }
        __syncthreads();   // compute on cur done before next-iter issue reuses it
    }

    // ---- normalize + transpose via smem + fused epilogue ----
    rs0 += __shfl_xor_sync(0xffffffffu, rs0, 1);
    rs0 += __shfl_xor_sync(0xffffffffu, rs0, 2);
    rs1 += __shfl_xor_sync(0xffffffffu, rs1, 1);
    rs1 += __shfl_xor_sync(0xffffffffu, rs1, 2);
    const float inv0 = 1.0f / rs0, inv1 = 1.0f / rs1;

    const int r0 = wid*16 + g;
#pragma unroll
    for (int nt = 0; nt < 8; nt++) {
        int ch = nt*8 + 2*t;
        *reinterpret_cast<float2*>(t_s + r0*66 + ch) =
            make_float2(o[nt][0]*inv0, o[nt][1]*inv0);
        *reinterpret_cast<float2*>(t_s + (r0+8)*66 + ch) =
            make_float2(o[nt][2]*inv1, o[nt][3]*inv1);
    }
    __syncthreads();

    const float g2 = 2.0f * gamma[0];
    const int c  = tid >> 2;
    const int i0 = (tid & 3) * 32;
    const size_t base = ((size_t)(b*64 + c))*4096 + qt*128 + i0;
#pragma unroll
    for (int i4 = 0; i4 < 8; i4++) {
        float4 xv = *reinterpret_cast<const float4*>(x  + base + i4*4);
        float4 yv = *reinterpret_cast<const float4*>(gy + base + i4*4);
        float4 ov;
        ov.x = xv.x + 2.f*yv.x + g2*t_s[(i0 + i4*4 + 0)*66 + c];
        ov.y = xv.y + 2.f*yv.y + g2*t_s[(i0 + i4*4 + 1)*66 + c];
        ov.z = xv.z + 2.f*yv.z + g2*t_s[(i0 + i4*4 + 2)*66 + c];
        ov.w = xv.w + 2.f*yv.w + g2*t_s[(i0 + i4*4 + 3)*66 + c];
        *reinterpret_cast<float4*>(outp + base + i4*4) = ov;
    }
}

// ---------------- launch ----------------
extern "C" void kernel_launch(void* const* d_in, const int* in_sizes, int n_in,
                              void* d_out, int out_size) {
    const float* x     = (const float*)d_in[0];
    const float* cv1_w = (const float*)d_in[1];
    const float* bn1_g = (const float*)d_in[2];
    const float* bn1_b = (const float*)d_in[3];
    const float* bn1_m = (const float*)d_in[4];
    const float* bn1_v = (const float*)d_in[5];
    const float* cv2_w = (const float*)d_in[6];
    const float* bn2_g = (const float*)d_in[7];
    const float* bn2_b = (const float*)d_in[8];
    const float* bn2_m = (const float*)d_in[9];
    const float* bn2_v = (const float*)d_in[10];
    const float* q_w   = (const float*)d_in[11];
    const float* q_b   = (const float*)d_in[12];
    const float* k_w   = (const float*)d_in[13];
    const float* k_b   = (const float*)d_in[14];
    const float* v_w   = (const float*)d_in[15];
    const float* v_b   = (const float*)d_in[16];
    const float* gamma = (const float*)d_in[17];
    float* out = (float*)d_out;

    void *py1, *py, *pq, *pk, *pvt;
    cudaGetSymbolAddress(&py1, g_y1);
    cudaGetSymbolAddress(&py,  g_y);
    cudaGetSymbolAddress(&pq,  g_q);
    cudaGetSymbolAddress(&pk,  g_k);
    cudaGetSymbolAddress(&pvt, g_vt);

    const int SMEM_C1 = (3840 + 32*296) * 4;     // 53248
    const int SMEM_C2 = (6400 + 32*64*12) * 4;   // 123904
    const int SMEM_FL = 3*2048 + 3*17408;        // 58368

    cudaFuncSetAttribute(conv1_kernel, cudaFuncAttributeMaxDynamicSharedMemorySize, SMEM_C1);
    cudaFuncSetAttribute(conv2_qkv_kernel, cudaFuncAttributeMaxDynamicSharedMemorySize, SMEM_C2);
    cudaFuncSetAttribute(flash_hmma_kernel, cudaFuncAttributeMaxDynamicSharedMemorySize, SMEM_FL);

    conv1_kernel<<<dim3(8,8,4), 256, SMEM_C1>>>(
        x, cv1_w, bn1_g, bn1_b, bn1_m, bn1_v, (float*)py1);
    conv2_qkv_kernel<<<dim3(4,8,4), 256, SMEM_C2>>>(
        (const float*)py1, cv2_w, bn2_g, bn2_b, bn2_m, bn2_v,
        q_w, q_b, k_w, k_b, v_w, v_b,
        (float*)py, (uint32_t*)pq, (uint32_t*)pk, (uint32_t*)pvt);
    flash_hmma_kernel<<<dim3(32,4), 256, SMEM_FL>>>(
        (const uint32_t*)pq, (const uint32_t*)pk, (const uint32_t*)pvt,
        x, (const float*)py, gamma, out);
}